// round 7
// baseline (speedup 1.0000x reference)
#include <cuda_runtime.h>
#include <cuda_bf16.h>
#include <cstdint>

// Problem constants
#define N_SRC1  292864
#define N_DST1  11264
#define N_E1    281600
#define N_DST2  1024
#define N_E2    10240
#define IN_DIM  256
#define H_DIM   256
#define C_DIM   47

// Scratch (device globals — no allocation allowed)
__device__ __nv_bfloat16 g_Ahi[N_DST1 * 512];
__device__ __nv_bfloat16 g_Alo[N_DST1 * 512];
__device__ __nv_bfloat16 g_WThi[256 * 512];
__device__ __nv_bfloat16 g_WTlo[256 * 512];
__device__ float g_h[N_DST1 * H_DIM];

// ---------------------------------------------------------------------------
// bf16 split helpers
// ---------------------------------------------------------------------------
__device__ __forceinline__ uint32_t pack_bf16x2(float f0, float f1) {
    const __nv_bfloat16 b0 = __float2bfloat16_rn(f0);
    const __nv_bfloat16 b1 = __float2bfloat16_rn(f1);
    return (uint32_t)__bfloat16_as_ushort(b0) | ((uint32_t)__bfloat16_as_ushort(b1) << 16);
}
__device__ __forceinline__ void split4(float4 v, float4& hi, float4& lo) {
    hi.x = __bfloat162float(__float2bfloat16_rn(v.x)); lo.x = v.x - hi.x;
    hi.y = __bfloat162float(__float2bfloat16_rn(v.y)); lo.y = v.y - hi.y;
    hi.z = __bfloat162float(__float2bfloat16_rn(v.z)); lo.z = v.z - hi.z;
    hi.w = __bfloat162float(__float2bfloat16_rn(v.w)); lo.w = v.w - hi.w;
}
__device__ __forceinline__ void store_bf16x4(__nv_bfloat16* p, float4 v) {
    uint2 u;
    u.x = pack_bf16x2(v.x, v.y);
    u.y = pack_bf16x2(v.z, v.w);
    *reinterpret_cast<uint2*>(p) = u;
}

// ---------------------------------------------------------------------------
// Layer-1 mean aggregation: bf16 hi/lo into A cols [256,512)
// ---------------------------------------------------------------------------
__global__ __launch_bounds__(64) void agg1_kernel(const float* __restrict__ feat,
                                                  const int* __restrict__ src_idx,
                                                  const int* __restrict__ dst_idx,
                                                  __nv_bfloat16* __restrict__ Ahi,
                                                  __nv_bfloat16* __restrict__ Alo)
{
    const int d = blockIdx.x;

    int lo = 0, hi = N_E1;
    while (lo < hi) { int mid = (lo + hi) >> 1; if (__ldg(&dst_idx[mid]) < d) lo = mid + 1; else hi = mid; }
    const int start = lo;
    hi = N_E1;
    while (lo < hi) { int mid = (lo + hi) >> 1; if (__ldg(&dst_idx[mid]) <= d) lo = mid + 1; else hi = mid; }
    const int end = lo;

    const int t = threadIdx.x;

    float4 a0 = make_float4(0.f,0.f,0.f,0.f);
    float4 a1 = make_float4(0.f,0.f,0.f,0.f);
    float4 a2 = make_float4(0.f,0.f,0.f,0.f);
    float4 a3 = make_float4(0.f,0.f,0.f,0.f);

    int e = start;
    for (; e + 3 < end; e += 4) {
        const int s0 = __ldg(&src_idx[e]);
        const int s1 = __ldg(&src_idx[e + 1]);
        const int s2 = __ldg(&src_idx[e + 2]);
        const int s3 = __ldg(&src_idx[e + 3]);
        const float4 v0 = *reinterpret_cast<const float4*>(&feat[(size_t)s0 * 256 + t * 4]);
        const float4 v1 = *reinterpret_cast<const float4*>(&feat[(size_t)s1 * 256 + t * 4]);
        const float4 v2 = *reinterpret_cast<const float4*>(&feat[(size_t)s2 * 256 + t * 4]);
        const float4 v3 = *reinterpret_cast<const float4*>(&feat[(size_t)s3 * 256 + t * 4]);
        a0.x += v0.x; a0.y += v0.y; a0.z += v0.z; a0.w += v0.w;
        a1.x += v1.x; a1.y += v1.y; a1.z += v1.z; a1.w += v1.w;
        a2.x += v2.x; a2.y += v2.y; a2.z += v2.z; a2.w += v2.w;
        a3.x += v3.x; a3.y += v3.y; a3.z += v3.z; a3.w += v3.w;
    }
    for (; e < end; ++e) {
        const int s = __ldg(&src_idx[e]);
        const float4 v = *reinterpret_cast<const float4*>(&feat[(size_t)s * 256 + t * 4]);
        a0.x += v.x; a0.y += v.y; a0.z += v.z; a0.w += v.w;
    }
    a0.x += a1.x + a2.x + a3.x;
    a0.y += a1.y + a2.y + a3.y;
    a0.z += a1.z + a2.z + a3.z;
    a0.w += a1.w + a2.w + a3.w;

    const int deg = end - start;
    const float inv = (deg > 0) ? 1.0f / (float)deg : 0.0f;
    a0.x *= inv; a0.y *= inv; a0.z *= inv; a0.w *= inv;

    float4 vh, vl;
    split4(a0, vh, vl);
    const size_t off = (size_t)d * 512 + 256 + t * 4;
    store_bf16x4(&Ahi[off], vh);
    store_bf16x4(&Alo[off], vl);
}

// ---------------------------------------------------------------------------
// Convert x[:11264] into A columns [0,256) (bf16 hi/lo).
// ---------------------------------------------------------------------------
__global__ __launch_bounds__(256) void xcvt_kernel(const float* __restrict__ x,
                                                   __nv_bfloat16* __restrict__ Ahi,
                                                   __nv_bfloat16* __restrict__ Alo)
{
    const int idx = blockIdx.x * 256 + threadIdx.x;
    const int r  = idx >> 6;
    const int c4 = (idx & 63) * 4;
    const float4 v = *reinterpret_cast<const float4*>(&x[(size_t)r * 256 + c4]);
    float4 vh, vl;
    split4(v, vh, vl);
    const size_t off = (size_t)r * 512 + c4;
    store_bf16x4(&Ahi[off], vh);
    store_bf16x4(&Alo[off], vl);
}

// ---------------------------------------------------------------------------
// Transpose + convert W: WT[n][k] = (k<256 ? Wself[k][n] : Wneigh[k-256][n])
// ---------------------------------------------------------------------------
__global__ __launch_bounds__(256) void wcvt_kernel(const float* __restrict__ Wself,
                                                   const float* __restrict__ Wneigh,
                                                   __nv_bfloat16* __restrict__ WThi,
                                                   __nv_bfloat16* __restrict__ WTlo)
{
    const int idx = blockIdx.x * 256 + threadIdx.x;
    const int n = idx >> 9;
    const int k = idx & 511;
    const float v = (k < 256) ? __ldg(&Wself[(size_t)k * 256 + n])
                              : __ldg(&Wneigh[(size_t)(k - 256) * 256 + n]);
    const float h = __bfloat162float(__float2bfloat16_rn(v));
    WThi[(size_t)n * 512 + k] = __float2bfloat16_rn(v);
    WTlo[(size_t)n * 512 + k] = __float2bfloat16_rn(v - h);
}

// ---------------------------------------------------------------------------
// cp.async / ldmatrix helpers
// ---------------------------------------------------------------------------
__device__ __forceinline__ void cp_async16(uint32_t saddr, const void* g) {
    asm volatile("cp.async.ca.shared.global [%0], [%1], 16;\n" :: "r"(saddr), "l"(g));
}
__device__ __forceinline__ void cp_commit() {
    asm volatile("cp.async.commit_group;\n" ::: "memory");
}
__device__ __forceinline__ void cp_wait0() {
    asm volatile("cp.async.wait_group 0;\n" ::: "memory");
}
__device__ __forceinline__ void ldsm_x4(uint32_t& r0, uint32_t& r1, uint32_t& r2, uint32_t& r3,
                                        uint32_t addr) {
    asm volatile("ldmatrix.sync.aligned.m8n8.x4.shared.b16 {%0,%1,%2,%3}, [%4];\n"
                 : "=r"(r0), "=r"(r1), "=r"(r2), "=r"(r3) : "r"(addr));
}
__device__ __forceinline__ void mma_bf16(float c[4], const uint32_t a[4], const uint32_t b[2]) {
    asm volatile(
        "mma.sync.aligned.m16n8k16.row.col.f32.bf16.bf16.f32 "
        "{%0,%1,%2,%3}, {%4,%5,%6,%7}, {%8,%9}, {%0,%1,%2,%3};\n"
        : "+f"(c[0]), "+f"(c[1]), "+f"(c[2]), "+f"(c[3])
        : "r"(a[0]), "r"(a[1]), "r"(a[2]), "r"(a[3]), "r"(b[0]), "r"(b[1]));
}

// ---------------------------------------------------------------------------
// Layer-1 GEMM: h = relu(A @ WT^T + b), 3xBF16 hi/lo via mma.m16n8k16.
// A [11264 x 512] bf16 (hi/lo), WT [256 x 512] bf16 (hi/lo).
// CTA 128x128, BK=16, 8 warps (warp 32x64), cp.async double buffer + ldmatrix.
// Shared rows: 12-word (48B) stride -> conflict-free LDSM phases.
// ---------------------------------------------------------------------------
#define G1_BM 128
#define G1_BN 128
#define SAW 12
// word offsets within a stage
#define OFF_AH 0
#define OFF_AL (G1_BM * SAW)                    // 1536
#define OFF_BH (2 * G1_BM * SAW)                // 3072
#define OFF_BL (2 * G1_BM * SAW + G1_BN * SAW)  // 4608
#define STAGE_WORDS (2 * G1_BM * SAW + 2 * G1_BN * SAW)  // 6144 (24KB)

__global__ __launch_bounds__(256) void gemm1_kernel(
    const __nv_bfloat16* __restrict__ Ahi,
    const __nv_bfloat16* __restrict__ Alo,
    const __nv_bfloat16* __restrict__ WThi,
    const __nv_bfloat16* __restrict__ WTlo,
    const float* __restrict__ bias,
    float* __restrict__ out)
{
    const int bx = blockIdx.x;          // 0..1 (N tiles of 128)
    const int by = blockIdx.y;          // 0..87

    const int tid  = threadIdx.x;
    const int warp = tid >> 5;
    const int lane = tid & 31;
    const int wm   = warp >> 1;         // 0..3 (32 rows)
    const int wn   = warp & 1;          // 0..1 (64 cols)
    const int g    = lane >> 2;
    const int tg   = lane & 3;

    __shared__ __align__(16) uint32_t smem[2 * STAGE_WORDS];   // 48KB

    uint32_t sbase;
    asm("{ .reg .u64 t; cvta.to.shared.u64 t, %1; cvt.u32.u64 %0, t; }"
        : "=r"(sbase) : "l"(smem));

    // ---- cp.async staging maps ----
    // A: 128 rows x 2 chunks (8 bf16 = 16B); thread -> (row, chunk), hi+lo.
    // B: identical mapping over 128 n-rows.
    const int s_row = tid >> 1;
    const int s_ch  = tid & 1;

    const __nv_bfloat16* gA_hi = Ahi + (size_t)(by * G1_BM + s_row) * 512 + s_ch * 8;
    const __nv_bfloat16* gA_lo = Alo + (size_t)(by * G1_BM + s_row) * 512 + s_ch * 8;
    const __nv_bfloat16* gB_hi = WThi + (size_t)(bx * G1_BN + s_row) * 512 + s_ch * 8;
    const __nv_bfloat16* gB_lo = WTlo + (size_t)(bx * G1_BN + s_row) * 512 + s_ch * 8;

    const uint32_t sA_hi = sbase + (OFF_AH + s_row * SAW + s_ch * 4) * 4;
    const uint32_t sA_lo = sbase + (OFF_AL + s_row * SAW + s_ch * 4) * 4;
    const uint32_t sB_hi = sbase + (OFF_BH + s_row * SAW + s_ch * 4) * 4;
    const uint32_t sB_lo = sbase + (OFF_BL + s_row * SAW + s_ch * 4) * 4;

    // ---- ldmatrix address maps (stage 0) ----
    // A tile i (i=0,1): rows wm*32 + i*16 + (lane&15), word (lane>>4)*4
    uint32_t aAddr[2];
#pragma unroll
    for (int i = 0; i < 2; ++i) {
        const int row = wm * 32 + i * 16 + (lane & 15);
        const int word = (lane >> 4) * 4;
        aAddr[i] = sbase + (OFF_AH + row * SAW + word) * 4;
    }
    // B tile p (p=0..3, 16 n each): rows wn*64 + p*16 + (lane&7) + ((lane>>4)<<3),
    // word ((lane>>3)&1)*4
    uint32_t bAddr[4];
#pragma unroll
    for (int p = 0; p < 4; ++p) {
        const int row = wn * 64 + p * 16 + (lane & 7) + ((lane >> 4) << 3);
        const int word = ((lane >> 3) & 1) * 4;
        bAddr[p] = sbase + (OFF_BH + row * SAW + word) * 4;
    }
    const uint32_t stage_bytes = STAGE_WORDS * 4;
    const uint32_t AL_off = (OFF_AL - OFF_AH) * 4;
    const uint32_t BL_off = (OFF_BL - OFF_BH) * 4;

    float acc[2][8][4];
#pragma unroll
    for (int i = 0; i < 2; ++i)
#pragma unroll
        for (int j = 0; j < 8; ++j)
#pragma unroll
            for (int r = 0; r < 4; ++r) acc[i][j][r] = 0.f;

    // ---- prologue: stage 0 = k-tile 0 ----
    cp_async16(sA_hi, gA_hi);
    cp_async16(sA_lo, gA_lo);
    cp_async16(sB_hi, gB_hi);
    cp_async16(sB_lo, gB_lo);
    cp_commit();

    for (int t = 0; t < 32; ++t) {
        cp_wait0();
        __syncthreads();

        if (t + 1 < 32) {
            const int kn = (t + 1) * 16;
            const uint32_t so = ((t + 1) & 1) * stage_bytes;
            cp_async16(sA_hi + so, gA_hi + kn);
            cp_async16(sA_lo + so, gA_lo + kn);
            cp_async16(sB_hi + so, gB_hi + kn);
            cp_async16(sB_lo + so, gB_lo + kn);
            cp_commit();
        }

        const uint32_t so = (t & 1) * stage_bytes;
        uint32_t Ah[2][4], Al[2][4], Bh[4][4], Bl[4][4];
#pragma unroll
        for (int i = 0; i < 2; ++i) {
            ldsm_x4(Ah[i][0], Ah[i][1], Ah[i][2], Ah[i][3], aAddr[i] + so);
            ldsm_x4(Al[i][0], Al[i][1], Al[i][2], Al[i][3], aAddr[i] + so + AL_off);
        }
#pragma unroll
        for (int p = 0; p < 4; ++p) {
            ldsm_x4(Bh[p][0], Bh[p][1], Bh[p][2], Bh[p][3], bAddr[p] + so);
            ldsm_x4(Bl[p][0], Bl[p][1], Bl[p][2], Bl[p][3], bAddr[p] + so + BL_off);
        }

        // 3xBF16: lo*hi + hi*lo + hi*hi
#pragma unroll
        for (int i = 0; i < 2; ++i)
#pragma unroll
            for (int j = 0; j < 8; ++j) {
                const uint32_t bf[2] = { Bh[j >> 1][(j & 1) * 2], Bh[j >> 1][(j & 1) * 2 + 1] };
                mma_bf16(acc[i][j], Al[i], bf);
            }
#pragma unroll
        for (int i = 0; i < 2; ++i)
#pragma unroll
            for (int j = 0; j < 8; ++j) {
                const uint32_t bf[2] = { Bl[j >> 1][(j & 1) * 2], Bl[j >> 1][(j & 1) * 2 + 1] };
                mma_bf16(acc[i][j], Ah[i], bf);
            }
#pragma unroll
        for (int i = 0; i < 2; ++i)
#pragma unroll
            for (int j = 0; j < 8; ++j) {
                const uint32_t bf[2] = { Bh[j >> 1][(j & 1) * 2], Bh[j >> 1][(j & 1) * 2 + 1] };
                mma_bf16(acc[i][j], Ah[i], bf);
            }
    }

    // Epilogue: +bias, relu, float2 stores
#pragma unroll
    for (int i = 0; i < 2; ++i) {
#pragma unroll
        for (int j = 0; j < 8; ++j) {
            const int col = bx * G1_BN + wn * 64 + j * 8 + tg * 2;
            const float b0 = __ldg(&bias[col]);
            const float b1 = __ldg(&bias[col + 1]);
            const int r0 = by * G1_BM + wm * 32 + i * 16 + g;
            float2 v0;
            v0.x = fmaxf(acc[i][j][0] + b0, 0.f);
            v0.y = fmaxf(acc[i][j][1] + b1, 0.f);
            *reinterpret_cast<float2*>(&out[(size_t)r0 * 256 + col]) = v0;
            float2 v1;
            v1.x = fmaxf(acc[i][j][2] + b0, 0.f);
            v1.y = fmaxf(acc[i][j][3] + b1, 0.f);
            *reinterpret_cast<float2*>(&out[(size_t)(r0 + 8) * 256 + col]) = v1;
        }
    }
}

// ---------------------------------------------------------------------------
// Fused layer 2: gather-mean + tiny GEMM per output row.
// ---------------------------------------------------------------------------
__global__ __launch_bounds__(128) void layer2_fused_kernel(
    const float* __restrict__ h,
    const int* __restrict__ src2,
    const int* __restrict__ dst2,
    const float* __restrict__ Ws,
    const float* __restrict__ Wn,
    const float* __restrict__ bias,
    float* __restrict__ out)
{
    const int d = blockIdx.x;

    int lo = 0, hi = N_E2;
    while (lo < hi) { int mid = (lo + hi) >> 1; if (__ldg(&dst2[mid]) < d) lo = mid + 1; else hi = mid; }
    const int start = lo;
    hi = N_E2;
    while (lo < hi) { int mid = (lo + hi) >> 1; if (__ldg(&dst2[mid]) <= d) lo = mid + 1; else hi = mid; }
    const int end = lo;

    __shared__ float a_self[256];
    __shared__ float a_nb[2][256];
    __shared__ float part[94];

    const int t    = threadIdx.x;
    const int half = t >> 6;
    const int tt   = t & 63;

    if (half == 0) {
        *reinterpret_cast<float4*>(&a_self[tt * 4]) =
            *reinterpret_cast<const float4*>(&h[(size_t)d * 256 + tt * 4]);
    }

    float4 acc = make_float4(0.f, 0.f, 0.f, 0.f);
    for (int e = start + half; e < end; e += 2) {
        const int s = __ldg(&src2[e]);
        const float4 v = *reinterpret_cast<const float4*>(&h[(size_t)s * 256 + tt * 4]);
        acc.x += v.x; acc.y += v.y; acc.z += v.z; acc.w += v.w;
    }
    *reinterpret_cast<float4*>(&a_nb[half][tt * 4]) = acc;
    __syncthreads();

    const int deg = end - start;
    const float inv = (deg > 0) ? 1.0f / (float)deg : 0.0f;
    if (half == 0) {
        float4 u = *reinterpret_cast<float4*>(&a_nb[0][tt * 4]);
        const float4 w = *reinterpret_cast<float4*>(&a_nb[1][tt * 4]);
        u.x = (u.x + w.x) * inv; u.y = (u.y + w.y) * inv;
        u.z = (u.z + w.z) * inv; u.w = (u.w + w.w) * inv;
        *reinterpret_cast<float4*>(&a_nb[0][tt * 4]) = u;
    }
    __syncthreads();

    if (t < 94) {
        const int c  = (t < 47) ? t : t - 47;
        const int kb = (t < 47) ? 0 : 128;
        const float* as = &a_self[kb];
        const float* an = &a_nb[0][kb];
        float accS = 0.f, accN = 0.f;
#pragma unroll 8
        for (int k = 0; k < 128; ++k) {
            accS += as[k] * __ldg(&Ws[(size_t)(kb + k) * 47 + c]);
            accN += an[k] * __ldg(&Wn[(size_t)(kb + k) * 47 + c]);
        }
        part[t] = accS + accN;
    }
    __syncthreads();

    if (t < 47) {
        out[(size_t)d * 47 + t] = part[t] + part[t + 47] + __ldg(&bias[t]);
    }
}

// ---------------------------------------------------------------------------
// Launch
// ---------------------------------------------------------------------------
extern "C" void kernel_launch(void* const* d_in, const int* in_sizes, int n_in,
                              void* d_out, int out_size)
{
    const float* x       = (const float*)d_in[0];
    const int*   src1    = (const int*)  d_in[1];
    const int*   dst1    = (const int*)  d_in[2];
    const int*   src2    = (const int*)  d_in[3];
    const int*   dst2    = (const int*)  d_in[4];
    const float* Wself1  = (const float*)d_in[5];
    const float* Wneigh1 = (const float*)d_in[6];
    const float* b1      = (const float*)d_in[7];
    const float* Wself2  = (const float*)d_in[8];
    const float* Wneigh2 = (const float*)d_in[9];
    const float* b2      = (const float*)d_in[10];
    float* out = (float*)d_out;

    __nv_bfloat16 *Ahi, *Alo, *WThi, *WTlo;
    float* hbuf;
    cudaGetSymbolAddress((void**)&Ahi,  g_Ahi);
    cudaGetSymbolAddress((void**)&Alo,  g_Alo);
    cudaGetSymbolAddress((void**)&WThi, g_WThi);
    cudaGetSymbolAddress((void**)&WTlo, g_WTlo);
    cudaGetSymbolAddress((void**)&hbuf, g_h);

    // Prep: W transpose+convert, x convert, neighbor mean (+convert)
    wcvt_kernel<<<(256 * 512) / 256, 256>>>(Wself1, Wneigh1, WThi, WTlo);
    xcvt_kernel<<<(N_DST1 * 64) / 256, 256>>>(x, Ahi, Alo);
    agg1_kernel<<<N_DST1, 64>>>(x, src1, dst1, Ahi, Alo);

    // Layer 1 GEMM + bias + relu
    dim3 g1(H_DIM / G1_BN, N_DST1 / G1_BM);   // (2, 88)
    gemm1_kernel<<<g1, 256>>>(Ahi, Alo, WThi, WTlo, b1, hbuf);

    // Fused layer 2
    layer2_fused_kernel<<<N_DST2, 128>>>(hbuf, src2, dst2, Wself2, Wneigh2, b2, out);
}

// round 8
// speedup vs baseline: 1.0603x; 1.0603x over previous
#include <cuda_runtime.h>
#include <cuda_fp16.h>
#include <cstdint>

// Problem constants
#define N_SRC1  292864
#define N_DST1  11264
#define N_E1    281600
#define N_DST2  1024
#define N_E2    10240
#define IN_DIM  256
#define H_DIM   256
#define C_DIM   47

// Scratch (device globals — no allocation allowed)
// A = [x_dst | hneigh1] as fp16 hi/lo, [11264 x 512]
__device__ __half g_Ahi[N_DST1 * 512];
__device__ __half g_Alo[N_DST1 * 512];
// W^T = [Wself;Wneigh]^T as fp16 hi only, [256 n][512 k]
__device__ __half g_WThi[256 * 512];
__device__ float g_h[N_DST1 * H_DIM];

// ---------------------------------------------------------------------------
// fp16 split helpers
// ---------------------------------------------------------------------------
__device__ __forceinline__ uint32_t pack_h2(float f0, float f1) {
    const __half h0 = __float2half_rn(f0);
    const __half h1 = __float2half_rn(f1);
    return (uint32_t)__half_as_ushort(h0) | ((uint32_t)__half_as_ushort(h1) << 16);
}
__device__ __forceinline__ void split4h(float4 v, float4& hi, float4& lo) {
    hi.x = __half2float(__float2half_rn(v.x)); lo.x = v.x - hi.x;
    hi.y = __half2float(__float2half_rn(v.y)); lo.y = v.y - hi.y;
    hi.z = __half2float(__float2half_rn(v.z)); lo.z = v.z - hi.z;
    hi.w = __half2float(__float2half_rn(v.w)); lo.w = v.w - hi.w;
}
__device__ __forceinline__ void store_h4(__half* p, float4 v) {
    uint2 u;
    u.x = pack_h2(v.x, v.y);
    u.y = pack_h2(v.z, v.w);
    *reinterpret_cast<uint2*>(p) = u;
}

// ---------------------------------------------------------------------------
// Layer-1 mean aggregation: one block (64 thr) per dst, 8x unroll (MLP=8).
// Emits fp16 hi/lo into A columns [256,512).
// ---------------------------------------------------------------------------
__global__ __launch_bounds__(64) void agg1_kernel(const float* __restrict__ feat,
                                                  const int* __restrict__ src_idx,
                                                  const int* __restrict__ dst_idx,
                                                  __half* __restrict__ Ahi,
                                                  __half* __restrict__ Alo)
{
    const int d = blockIdx.x;

    int lo = 0, hi = N_E1;
    while (lo < hi) { int mid = (lo + hi) >> 1; if (__ldg(&dst_idx[mid]) < d) lo = mid + 1; else hi = mid; }
    const int start = lo;
    hi = N_E1;
    while (lo < hi) { int mid = (lo + hi) >> 1; if (__ldg(&dst_idx[mid]) <= d) lo = mid + 1; else hi = mid; }
    const int end = lo;

    const int t = threadIdx.x;

    float4 acc[8];
#pragma unroll
    for (int u = 0; u < 8; ++u) acc[u] = make_float4(0.f, 0.f, 0.f, 0.f);

    int e = start;
    for (; e + 7 < end; e += 8) {
        int s[8];
#pragma unroll
        for (int u = 0; u < 8; ++u) s[u] = __ldg(&src_idx[e + u]);
#pragma unroll
        for (int u = 0; u < 8; ++u) {
            const float4 v = *reinterpret_cast<const float4*>(&feat[(size_t)s[u] * 256 + t * 4]);
            acc[u].x += v.x; acc[u].y += v.y; acc[u].z += v.z; acc[u].w += v.w;
        }
    }
    for (; e < end; ++e) {
        const int s = __ldg(&src_idx[e]);
        const float4 v = *reinterpret_cast<const float4*>(&feat[(size_t)s * 256 + t * 4]);
        acc[0].x += v.x; acc[0].y += v.y; acc[0].z += v.z; acc[0].w += v.w;
    }
#pragma unroll
    for (int u = 1; u < 8; ++u) {
        acc[0].x += acc[u].x; acc[0].y += acc[u].y;
        acc[0].z += acc[u].z; acc[0].w += acc[u].w;
    }

    const int deg = end - start;
    const float inv = (deg > 0) ? 1.0f / (float)deg : 0.0f;
    acc[0].x *= inv; acc[0].y *= inv; acc[0].z *= inv; acc[0].w *= inv;

    float4 vh, vl;
    split4h(acc[0], vh, vl);
    const size_t off = (size_t)d * 512 + 256 + t * 4;
    store_h4(&Ahi[off], vh);
    store_h4(&Alo[off], vl);
}

// ---------------------------------------------------------------------------
// Convert x[:11264] into A columns [0,256) (fp16 hi/lo).
// ---------------------------------------------------------------------------
__global__ __launch_bounds__(256) void xcvt_kernel(const float* __restrict__ x,
                                                   __half* __restrict__ Ahi,
                                                   __half* __restrict__ Alo)
{
    const int idx = blockIdx.x * 256 + threadIdx.x;
    const int r  = idx >> 6;
    const int c4 = (idx & 63) * 4;
    const float4 v = *reinterpret_cast<const float4*>(&x[(size_t)r * 256 + c4]);
    float4 vh, vl;
    split4h(v, vh, vl);
    const size_t off = (size_t)r * 512 + c4;
    store_h4(&Ahi[off], vh);
    store_h4(&Alo[off], vl);
}

// ---------------------------------------------------------------------------
// Transpose + convert W (hi only): WT[n][k]
// ---------------------------------------------------------------------------
__global__ __launch_bounds__(256) void wcvt_kernel(const float* __restrict__ Wself,
                                                   const float* __restrict__ Wneigh,
                                                   __half* __restrict__ WThi)
{
    const int idx = blockIdx.x * 256 + threadIdx.x;
    const int n = idx >> 9;
    const int k = idx & 511;
    const float v = (k < 256) ? __ldg(&Wself[(size_t)k * 256 + n])
                              : __ldg(&Wneigh[(size_t)(k - 256) * 256 + n]);
    WThi[(size_t)n * 512 + k] = __float2half_rn(v);
}

// ---------------------------------------------------------------------------
// cp.async / ldmatrix helpers
// ---------------------------------------------------------------------------
__device__ __forceinline__ void cp_async16(uint32_t saddr, const void* g) {
    asm volatile("cp.async.ca.shared.global [%0], [%1], 16;\n" :: "r"(saddr), "l"(g));
}
__device__ __forceinline__ void cp_commit() {
    asm volatile("cp.async.commit_group;\n" ::: "memory");
}
__device__ __forceinline__ void cp_wait0() {
    asm volatile("cp.async.wait_group 0;\n" ::: "memory");
}
__device__ __forceinline__ void ldsm_x4(uint32_t& r0, uint32_t& r1, uint32_t& r2, uint32_t& r3,
                                        uint32_t addr) {
    asm volatile("ldmatrix.sync.aligned.m8n8.x4.shared.b16 {%0,%1,%2,%3}, [%4];\n"
                 : "=r"(r0), "=r"(r1), "=r"(r2), "=r"(r3) : "r"(addr));
}
__device__ __forceinline__ void mma_f16(float c[4], const uint32_t a[4], const uint32_t b[2]) {
    asm volatile(
        "mma.sync.aligned.m16n8k16.row.col.f32.f16.f16.f32 "
        "{%0,%1,%2,%3}, {%4,%5,%6,%7}, {%8,%9}, {%0,%1,%2,%3};\n"
        : "+f"(c[0]), "+f"(c[1]), "+f"(c[2]), "+f"(c[3])
        : "r"(a[0]), "r"(a[1]), "r"(a[2]), "r"(a[3]), "r"(b[0]), "r"(b[1]));
}

// ---------------------------------------------------------------------------
// Layer-1 GEMM: h = relu(A @ WT^T + b), 2-pass fp16 (Ah@Bh + Al@Bh).
// A [11264 x 512] fp16 hi/lo, WT [256 x 512] fp16 hi.
// CTA 128x64, BK=16, 8 warps (warp 32x32), cp.async double buffer + ldmatrix.
// Shared rows: 12-word (48B) stride -> conflict-free LDSM phases.
// ---------------------------------------------------------------------------
#define G1_BM 128
#define G1_BN 64
#define SAW 12
#define OFF_AH 0
#define OFF_AL (G1_BM * SAW)                 // 1536
#define OFF_BH (2 * G1_BM * SAW)             // 3072
#define STAGE_WORDS (2 * G1_BM * SAW + G1_BN * SAW)   // 3840 (15KB)

__global__ __launch_bounds__(256) void gemm1_kernel(
    const __half* __restrict__ Ahi,
    const __half* __restrict__ Alo,
    const __half* __restrict__ WThi,
    const float* __restrict__ bias,
    float* __restrict__ out)
{
    const int bx = blockIdx.x;          // 0..3 (N tiles of 64)
    const int by = blockIdx.y;          // 0..87

    const int tid  = threadIdx.x;
    const int warp = tid >> 5;
    const int lane = tid & 31;
    const int wm   = warp >> 1;         // 0..3
    const int wn   = warp & 1;          // 0..1
    const int g    = lane >> 2;
    const int tg   = lane & 3;

    __shared__ __align__(16) uint32_t smem[2 * STAGE_WORDS];   // 30KB

    uint32_t sbase;
    asm("{ .reg .u64 t; cvta.to.shared.u64 t, %1; cvt.u32.u64 %0, t; }"
        : "=r"(sbase) : "l"(smem));

    // ---- cp.async staging maps ----
    // A: 128 rows x 2 chunks; thread -> (row, chunk) for hi and lo.
    const int a_row = tid >> 1;
    const int a_ch  = tid & 1;
    // B: 64 rows x 2 chunks = 128 slots; threads 0..127 handle B, 128..255 idle.
    const int b_row = (tid & 127) >> 1;
    const int b_ch  = tid & 1;
    const bool do_b = (tid < 128);

    const __half* gA_hi = Ahi + (size_t)(by * G1_BM + a_row) * 512 + a_ch * 8;
    const __half* gA_lo = Alo + (size_t)(by * G1_BM + a_row) * 512 + a_ch * 8;
    const __half* gB    = WThi + (size_t)(bx * G1_BN + b_row) * 512 + b_ch * 8;

    const uint32_t sA_hi = sbase + (OFF_AH + a_row * SAW + a_ch * 4) * 4;
    const uint32_t sA_lo = sbase + (OFF_AL + a_row * SAW + a_ch * 4) * 4;
    const uint32_t sB    = sbase + (OFF_BH + b_row * SAW + b_ch * 4) * 4;

    // ---- ldmatrix address maps ----
    uint32_t aAddr[2];
#pragma unroll
    for (int i = 0; i < 2; ++i) {
        const int row = wm * 32 + i * 16 + (lane & 15);
        const int word = (lane >> 4) * 4;
        aAddr[i] = sbase + (OFF_AH + row * SAW + word) * 4;
    }
    uint32_t bAddr[2];
#pragma unroll
    for (int p = 0; p < 2; ++p) {
        const int row = wn * 32 + p * 16 + (lane & 7) + ((lane >> 4) << 3);
        const int word = ((lane >> 3) & 1) * 4;
        bAddr[p] = sbase + (OFF_BH + row * SAW + word) * 4;
    }
    const uint32_t stage_bytes = STAGE_WORDS * 4;
    const uint32_t AL_off = (OFF_AL - OFF_AH) * 4;

    float acc[2][4][4];
#pragma unroll
    for (int i = 0; i < 2; ++i)
#pragma unroll
        for (int j = 0; j < 4; ++j)
#pragma unroll
            for (int r = 0; r < 4; ++r) acc[i][j][r] = 0.f;

    // ---- prologue ----
    cp_async16(sA_hi, gA_hi);
    cp_async16(sA_lo, gA_lo);
    if (do_b) cp_async16(sB, gB);
    cp_commit();

    for (int t = 0; t < 32; ++t) {
        cp_wait0();
        __syncthreads();

        if (t + 1 < 32) {
            const int kn = (t + 1) * 16;
            const uint32_t so = ((t + 1) & 1) * stage_bytes;
            cp_async16(sA_hi + so, gA_hi + kn);
            cp_async16(sA_lo + so, gA_lo + kn);
            if (do_b) cp_async16(sB + so, gB + kn);
            cp_commit();
        }

        const uint32_t so = (t & 1) * stage_bytes;
        uint32_t Ah[2][4], Al[2][4], Bh[2][4];
#pragma unroll
        for (int i = 0; i < 2; ++i) {
            ldsm_x4(Ah[i][0], Ah[i][1], Ah[i][2], Ah[i][3], aAddr[i] + so);
            ldsm_x4(Al[i][0], Al[i][1], Al[i][2], Al[i][3], aAddr[i] + so + AL_off);
        }
#pragma unroll
        for (int p = 0; p < 2; ++p) {
            ldsm_x4(Bh[p][0], Bh[p][1], Bh[p][2], Bh[p][3], bAddr[p] + so);
        }

        // 2-pass fp16: Al*Bh + Ah*Bh
#pragma unroll
        for (int i = 0; i < 2; ++i)
#pragma unroll
            for (int j = 0; j < 4; ++j) {
                const uint32_t bf[2] = { Bh[j >> 1][(j & 1) * 2], Bh[j >> 1][(j & 1) * 2 + 1] };
                mma_f16(acc[i][j], Al[i], bf);
            }
#pragma unroll
        for (int i = 0; i < 2; ++i)
#pragma unroll
            for (int j = 0; j < 4; ++j) {
                const uint32_t bf[2] = { Bh[j >> 1][(j & 1) * 2], Bh[j >> 1][(j & 1) * 2 + 1] };
                mma_f16(acc[i][j], Ah[i], bf);
            }
    }

    // Epilogue: +bias, relu, float2 stores
#pragma unroll
    for (int i = 0; i < 2; ++i) {
#pragma unroll
        for (int j = 0; j < 4; ++j) {
            const int col = bx * G1_BN + wn * 32 + j * 8 + tg * 2;
            const float b0 = __ldg(&bias[col]);
            const float b1 = __ldg(&bias[col + 1]);
            const int r0 = by * G1_BM + wm * 32 + i * 16 + g;
            float2 v0;
            v0.x = fmaxf(acc[i][j][0] + b0, 0.f);
            v0.y = fmaxf(acc[i][j][1] + b1, 0.f);
            *reinterpret_cast<float2*>(&out[(size_t)r0 * 256 + col]) = v0;
            float2 v1;
            v1.x = fmaxf(acc[i][j][2] + b0, 0.f);
            v1.y = fmaxf(acc[i][j][3] + b1, 0.f);
            *reinterpret_cast<float2*>(&out[(size_t)(r0 + 8) * 256 + col]) = v1;
        }
    }
}

// ---------------------------------------------------------------------------
// Fused layer 2: gather-mean + tiny GEMM per output row.
// ---------------------------------------------------------------------------
__global__ __launch_bounds__(128) void layer2_fused_kernel(
    const float* __restrict__ h,
    const int* __restrict__ src2,
    const int* __restrict__ dst2,
    const float* __restrict__ Ws,
    const float* __restrict__ Wn,
    const float* __restrict__ bias,
    float* __restrict__ out)
{
    const int d = blockIdx.x;

    int lo = 0, hi = N_E2;
    while (lo < hi) { int mid = (lo + hi) >> 1; if (__ldg(&dst2[mid]) < d) lo = mid + 1; else hi = mid; }
    const int start = lo;
    hi = N_E2;
    while (lo < hi) { int mid = (lo + hi) >> 1; if (__ldg(&dst2[mid]) <= d) lo = mid + 1; else hi = mid; }
    const int end = lo;

    __shared__ float a_self[256];
    __shared__ float a_nb[2][256];
    __shared__ float part[94];

    const int t    = threadIdx.x;
    const int half = t >> 6;
    const int tt   = t & 63;

    if (half == 0) {
        *reinterpret_cast<float4*>(&a_self[tt * 4]) =
            *reinterpret_cast<const float4*>(&h[(size_t)d * 256 + tt * 4]);
    }

    float4 acc = make_float4(0.f, 0.f, 0.f, 0.f);
    for (int e = start + half; e < end; e += 2) {
        const int s = __ldg(&src2[e]);
        const float4 v = *reinterpret_cast<const float4*>(&h[(size_t)s * 256 + tt * 4]);
        acc.x += v.x; acc.y += v.y; acc.z += v.z; acc.w += v.w;
    }
    *reinterpret_cast<float4*>(&a_nb[half][tt * 4]) = acc;
    __syncthreads();

    const int deg = end - start;
    const float inv = (deg > 0) ? 1.0f / (float)deg : 0.0f;
    if (half == 0) {
        float4 u = *reinterpret_cast<float4*>(&a_nb[0][tt * 4]);
        const float4 w = *reinterpret_cast<float4*>(&a_nb[1][tt * 4]);
        u.x = (u.x + w.x) * inv; u.y = (u.y + w.y) * inv;
        u.z = (u.z + w.z) * inv; u.w = (u.w + w.w) * inv;
        *reinterpret_cast<float4*>(&a_nb[0][tt * 4]) = u;
    }
    __syncthreads();

    if (t < 94) {
        const int c  = (t < 47) ? t : t - 47;
        const int kb = (t < 47) ? 0 : 128;
        const float* as = &a_self[kb];
        const float* an = &a_nb[0][kb];
        float accS = 0.f, accN = 0.f;
#pragma unroll 8
        for (int k = 0; k < 128; ++k) {
            accS += as[k] * __ldg(&Ws[(size_t)(kb + k) * 47 + c]);
            accN += an[k] * __ldg(&Wn[(size_t)(kb + k) * 47 + c]);
        }
        part[t] = accS + accN;
    }
    __syncthreads();

    if (t < 47) {
        out[(size_t)d * 47 + t] = part[t] + part[t + 47] + __ldg(&bias[t]);
    }
}

// ---------------------------------------------------------------------------
// Launch
// ---------------------------------------------------------------------------
extern "C" void kernel_launch(void* const* d_in, const int* in_sizes, int n_in,
                              void* d_out, int out_size)
{
    const float* x       = (const float*)d_in[0];
    const int*   src1    = (const int*)  d_in[1];
    const int*   dst1    = (const int*)  d_in[2];
    const int*   src2    = (const int*)  d_in[3];
    const int*   dst2    = (const int*)  d_in[4];
    const float* Wself1  = (const float*)d_in[5];
    const float* Wneigh1 = (const float*)d_in[6];
    const float* b1      = (const float*)d_in[7];
    const float* Wself2  = (const float*)d_in[8];
    const float* Wneigh2 = (const float*)d_in[9];
    const float* b2      = (const float*)d_in[10];
    float* out = (float*)d_out;

    __half *Ahi, *Alo, *WThi;
    float* hbuf;
    cudaGetSymbolAddress((void**)&Ahi,  g_Ahi);
    cudaGetSymbolAddress((void**)&Alo,  g_Alo);
    cudaGetSymbolAddress((void**)&WThi, g_WThi);
    cudaGetSymbolAddress((void**)&hbuf, g_h);

    // Prep: W transpose+convert, x convert, neighbor mean (+convert)
    wcvt_kernel<<<(256 * 512) / 256, 256>>>(Wself1, Wneigh1, WThi);
    xcvt_kernel<<<(N_DST1 * 64) / 256, 256>>>(x, Ahi, Alo);
    agg1_kernel<<<N_DST1, 64>>>(x, src1, dst1, Ahi, Alo);

    // Layer 1 GEMM + bias + relu (2-pass fp16)
    dim3 g1(H_DIM / G1_BN, N_DST1 / G1_BM);   // (4, 88)
    gemm1_kernel<<<g1, 256>>>(Ahi, Alo, WThi, b1, hbuf);

    // Fused layer 2
    layer2_fused_kernel<<<N_DST2, 128>>>(hbuf, src2, dst2, Wself2, Wneigh2, b2, out);
}

// round 9
// speedup vs baseline: 1.1612x; 1.0951x over previous
#include <cuda_runtime.h>
#include <cuda_fp16.h>
#include <cstdint>

// Problem constants
#define N_SRC1  292864
#define N_DST1  11264
#define N_E1    281600
#define N_DST2  1024
#define N_E2    10240
#define IN_DIM  256
#define H_DIM   256
#define C_DIM   47

// Scratch (device globals — no allocation allowed)
// A = [x_dst | hneigh1] as fp16, [11264 x 512]
__device__ __half g_A[N_DST1 * 512];
// W^T = [Wself;Wneigh]^T as fp16, [256 n][512 k]
__device__ __half g_WT[256 * 512];
__device__ float g_h[N_DST1 * H_DIM];

// ---------------------------------------------------------------------------
// fp16 helpers
// ---------------------------------------------------------------------------
__device__ __forceinline__ uint32_t pack_h2(float f0, float f1) {
    const __half h0 = __float2half_rn(f0);
    const __half h1 = __float2half_rn(f1);
    return (uint32_t)__half_as_ushort(h0) | ((uint32_t)__half_as_ushort(h1) << 16);
}
__device__ __forceinline__ void store_h4(__half* p, float4 v) {
    uint2 u;
    u.x = pack_h2(v.x, v.y);
    u.y = pack_h2(v.z, v.w);
    *reinterpret_cast<uint2*>(p) = u;
}

// ---------------------------------------------------------------------------
// Layer-1 mean aggregation: one block (64 thr) per dst, 8x unroll (MLP=8).
// Emits fp16 into A columns [256,512).
// ---------------------------------------------------------------------------
__global__ __launch_bounds__(64) void agg1_kernel(const float* __restrict__ feat,
                                                  const int* __restrict__ src_idx,
                                                  const int* __restrict__ dst_idx,
                                                  __half* __restrict__ A)
{
    const int d = blockIdx.x;

    int lo = 0, hi = N_E1;
    while (lo < hi) { int mid = (lo + hi) >> 1; if (__ldg(&dst_idx[mid]) < d) lo = mid + 1; else hi = mid; }
    const int start = lo;
    hi = N_E1;
    while (lo < hi) { int mid = (lo + hi) >> 1; if (__ldg(&dst_idx[mid]) <= d) lo = mid + 1; else hi = mid; }
    const int end = lo;

    const int t = threadIdx.x;

    float4 acc[8];
#pragma unroll
    for (int u = 0; u < 8; ++u) acc[u] = make_float4(0.f, 0.f, 0.f, 0.f);

    int e = start;
    for (; e + 7 < end; e += 8) {
        int s[8];
#pragma unroll
        for (int u = 0; u < 8; ++u) s[u] = __ldg(&src_idx[e + u]);
#pragma unroll
        for (int u = 0; u < 8; ++u) {
            const float4 v = *reinterpret_cast<const float4*>(&feat[(size_t)s[u] * 256 + t * 4]);
            acc[u].x += v.x; acc[u].y += v.y; acc[u].z += v.z; acc[u].w += v.w;
        }
    }
    for (; e < end; ++e) {
        const int s = __ldg(&src_idx[e]);
        const float4 v = *reinterpret_cast<const float4*>(&feat[(size_t)s * 256 + t * 4]);
        acc[0].x += v.x; acc[0].y += v.y; acc[0].z += v.z; acc[0].w += v.w;
    }
#pragma unroll
    for (int u = 1; u < 8; ++u) {
        acc[0].x += acc[u].x; acc[0].y += acc[u].y;
        acc[0].z += acc[u].z; acc[0].w += acc[u].w;
    }

    const int deg = end - start;
    const float inv = (deg > 0) ? 1.0f / (float)deg : 0.0f;
    acc[0].x *= inv; acc[0].y *= inv; acc[0].z *= inv; acc[0].w *= inv;

    store_h4(&A[(size_t)d * 512 + 256 + t * 4], acc[0]);
}

// ---------------------------------------------------------------------------
// Convert x[:11264] into A columns [0,256) (fp16).
// ---------------------------------------------------------------------------
__global__ __launch_bounds__(256) void xcvt_kernel(const float* __restrict__ x,
                                                   __half* __restrict__ A)
{
    const int idx = blockIdx.x * 256 + threadIdx.x;
    const int r  = idx >> 6;
    const int c4 = (idx & 63) * 4;
    const float4 v = *reinterpret_cast<const float4*>(&x[(size_t)r * 256 + c4]);
    store_h4(&A[(size_t)r * 512 + c4], v);
}

// ---------------------------------------------------------------------------
// Transpose + convert W: WT[n][k]
// ---------------------------------------------------------------------------
__global__ __launch_bounds__(256) void wcvt_kernel(const float* __restrict__ Wself,
                                                   const float* __restrict__ Wneigh,
                                                   __half* __restrict__ WT)
{
    const int idx = blockIdx.x * 256 + threadIdx.x;
    const int n = idx >> 9;
    const int k = idx & 511;
    const float v = (k < 256) ? __ldg(&Wself[(size_t)k * 256 + n])
                              : __ldg(&Wneigh[(size_t)(k - 256) * 256 + n]);
    WT[(size_t)n * 512 + k] = __float2half_rn(v);
}

// ---------------------------------------------------------------------------
// cp.async / ldmatrix helpers
// ---------------------------------------------------------------------------
__device__ __forceinline__ void cp_async16(uint32_t saddr, const void* g) {
    asm volatile("cp.async.ca.shared.global [%0], [%1], 16;\n" :: "r"(saddr), "l"(g));
}
__device__ __forceinline__ void cp_commit() {
    asm volatile("cp.async.commit_group;\n" ::: "memory");
}
__device__ __forceinline__ void ldsm_x4(uint32_t& r0, uint32_t& r1, uint32_t& r2, uint32_t& r3,
                                        uint32_t addr) {
    asm volatile("ldmatrix.sync.aligned.m8n8.x4.shared.b16 {%0,%1,%2,%3}, [%4];\n"
                 : "=r"(r0), "=r"(r1), "=r"(r2), "=r"(r3) : "r"(addr));
}
__device__ __forceinline__ void mma_f16(float c[4], const uint32_t a[4], const uint32_t b[2]) {
    asm volatile(
        "mma.sync.aligned.m16n8k16.row.col.f32.f16.f16.f32 "
        "{%0,%1,%2,%3}, {%4,%5,%6,%7}, {%8,%9}, {%0,%1,%2,%3};\n"
        : "+f"(c[0]), "+f"(c[1]), "+f"(c[2]), "+f"(c[3])
        : "r"(a[0]), "r"(a[1]), "r"(a[2]), "r"(a[3]), "r"(b[0]), "r"(b[1]));
}

// ---------------------------------------------------------------------------
// Layer-1 GEMM: h = relu(A @ WT^T + b), single-pass fp16 mma.m16n8k16.
// A [11264 x 512] fp16, WT [256 x 512] fp16.
// CTA 128x64, BK=32, 8 warps (warp 32x32), 3-stage cp.async ring + ldmatrix.
// Shared rows: 20-word (80B) stride -> conflict-free LDSM phases.
// ---------------------------------------------------------------------------
#define G1_BM 128
#define G1_BN 64
#define G1_BK 32
#define SRW 20                                  // words per row (16 data + 4 pad)
#define OFF_A 0
#define OFF_B (G1_BM * SRW)                     // 2560
#define STAGE_WORDS ((G1_BM + G1_BN) * SRW)     // 3840 words = 15KB
#define N_KTILES 16                             // 512 / 32

__global__ __launch_bounds__(256) void gemm1_kernel(
    const __half* __restrict__ A,
    const __half* __restrict__ WT,
    const float* __restrict__ bias,
    float* __restrict__ out)
{
    const int bx = blockIdx.x;          // 0..3 (N tiles of 64)
    const int by = blockIdx.y;          // 0..87

    const int tid  = threadIdx.x;
    const int warp = tid >> 5;
    const int lane = tid & 31;
    const int wm   = warp >> 1;         // 0..3
    const int wn   = warp & 1;          // 0..1
    const int g    = lane >> 2;
    const int tg   = lane & 3;

    __shared__ __align__(16) uint32_t smem[3 * STAGE_WORDS];   // 45KB

    uint32_t sbase;
    asm("{ .reg .u64 t; cvta.to.shared.u64 t, %1; cvt.u32.u64 %0, t; }"
        : "=r"(sbase) : "l"(smem));

    // ---- cp.async staging maps (per 32-k tile) ----
    // A: 128 rows x 4 chunks(16B) = 512 ops -> 2 per thread.
    // B: 64 rows x 4 chunks = 256 ops -> 1 per thread.
    const int a_row0 = tid >> 2;               // slot j: row = a_row0 + j*64
    const int a_ch   = tid & 3;
    const int b_row  = tid >> 2;               // 0..63
    const int b_ch   = tid & 3;

    const __half* gA0 = A  + (size_t)(by * G1_BM + a_row0) * 512 + a_ch * 8;
    const __half* gA1 = A  + (size_t)(by * G1_BM + a_row0 + 64) * 512 + a_ch * 8;
    const __half* gB  = WT + (size_t)(bx * G1_BN + b_row) * 512 + b_ch * 8;

    const uint32_t sA0 = sbase + (OFF_A + a_row0 * SRW + a_ch * 4) * 4;
    const uint32_t sA1 = sbase + (OFF_A + (a_row0 + 64) * SRW + a_ch * 4) * 4;
    const uint32_t sB  = sbase + (OFF_B + b_row * SRW + b_ch * 4) * 4;

    // ---- ldmatrix address maps (stage 0, k-step 0) ----
    uint32_t aAddr[2];
#pragma unroll
    for (int i = 0; i < 2; ++i) {
        const int row = wm * 32 + i * 16 + (lane & 15);
        const int word = (lane >> 4) * 4;
        aAddr[i] = sbase + (OFF_A + row * SRW + word) * 4;
    }
    uint32_t bAddr[2];
#pragma unroll
    for (int p = 0; p < 2; ++p) {
        const int row = wn * 32 + p * 16 + (lane & 7) + ((lane >> 4) << 3);
        const int word = ((lane >> 3) & 1) * 4;
        bAddr[p] = sbase + (OFF_B + row * SRW + word) * 4;
    }
    const uint32_t stage_bytes = STAGE_WORDS * 4;

    float acc[2][4][4];
#pragma unroll
    for (int i = 0; i < 2; ++i)
#pragma unroll
        for (int j = 0; j < 4; ++j)
#pragma unroll
            for (int r = 0; r < 4; ++r) acc[i][j][r] = 0.f;

    // ---- prologue: stage tiles 0 and 1 ----
#pragma unroll
    for (int pt = 0; pt < 2; ++pt) {
        const uint32_t so = pt * stage_bytes;
        const int kn = pt * G1_BK;
        cp_async16(sA0 + so, gA0 + kn);
        cp_async16(sA1 + so, gA1 + kn);
        cp_async16(sB + so,  gB + kn);
        cp_commit();
    }

    int stage = 0;
    for (int t = 0; t < N_KTILES; ++t) {
        if (t + 1 < N_KTILES)
            asm volatile("cp.async.wait_group 1;" ::: "memory");
        else
            asm volatile("cp.async.wait_group 0;" ::: "memory");
        __syncthreads();

        if (t + 2 < N_KTILES) {
            const int kn = (t + 2) * G1_BK;
            const uint32_t so = ((stage + 2) % 3) * stage_bytes;
            cp_async16(sA0 + so, gA0 + kn);
            cp_async16(sA1 + so, gA1 + kn);
            cp_async16(sB + so,  gB + kn);
            cp_commit();
        }

        const uint32_t so = stage * stage_bytes;
        // two k16 steps within the 32-k tile
#pragma unroll
        for (int s = 0; s < 2; ++s) {
            const uint32_t ko = so + s * 32;     // 8 words = 32B per k16
            uint32_t Af[2][4], Bf[2][4];
#pragma unroll
            for (int i = 0; i < 2; ++i)
                ldsm_x4(Af[i][0], Af[i][1], Af[i][2], Af[i][3], aAddr[i] + ko);
#pragma unroll
            for (int p = 0; p < 2; ++p)
                ldsm_x4(Bf[p][0], Bf[p][1], Bf[p][2], Bf[p][3], bAddr[p] + ko);
#pragma unroll
            for (int i = 0; i < 2; ++i)
#pragma unroll
                for (int j = 0; j < 4; ++j) {
                    const uint32_t bf[2] = { Bf[j >> 1][(j & 1) * 2], Bf[j >> 1][(j & 1) * 2 + 1] };
                    mma_f16(acc[i][j], Af[i], bf);
                }
        }
        stage = (stage + 1) % 3;
    }

    // Epilogue: +bias, relu, float2 stores
#pragma unroll
    for (int i = 0; i < 2; ++i) {
#pragma unroll
        for (int j = 0; j < 4; ++j) {
            const int col = bx * G1_BN + wn * 32 + j * 8 + tg * 2;
            const float b0 = __ldg(&bias[col]);
            const float b1 = __ldg(&bias[col + 1]);
            const int r0 = by * G1_BM + wm * 32 + i * 16 + g;
            float2 v0;
            v0.x = fmaxf(acc[i][j][0] + b0, 0.f);
            v0.y = fmaxf(acc[i][j][1] + b1, 0.f);
            *reinterpret_cast<float2*>(&out[(size_t)r0 * 256 + col]) = v0;
            float2 v1;
            v1.x = fmaxf(acc[i][j][2] + b0, 0.f);
            v1.y = fmaxf(acc[i][j][3] + b1, 0.f);
            *reinterpret_cast<float2*>(&out[(size_t)(r0 + 8) * 256 + col]) = v1;
        }
    }
}

// ---------------------------------------------------------------------------
// Fused layer 2: gather-mean + tiny GEMM per output row.
// ---------------------------------------------------------------------------
__global__ __launch_bounds__(128) void layer2_fused_kernel(
    const float* __restrict__ h,
    const int* __restrict__ src2,
    const int* __restrict__ dst2,
    const float* __restrict__ Ws,
    const float* __restrict__ Wn,
    const float* __restrict__ bias,
    float* __restrict__ out)
{
    const int d = blockIdx.x;

    int lo = 0, hi = N_E2;
    while (lo < hi) { int mid = (lo + hi) >> 1; if (__ldg(&dst2[mid]) < d) lo = mid + 1; else hi = mid; }
    const int start = lo;
    hi = N_E2;
    while (lo < hi) { int mid = (lo + hi) >> 1; if (__ldg(&dst2[mid]) <= d) lo = mid + 1; else hi = mid; }
    const int end = lo;

    __shared__ float a_self[256];
    __shared__ float a_nb[2][256];
    __shared__ float part[94];

    const int t    = threadIdx.x;
    const int half = t >> 6;
    const int tt   = t & 63;

    if (half == 0) {
        *reinterpret_cast<float4*>(&a_self[tt * 4]) =
            *reinterpret_cast<const float4*>(&h[(size_t)d * 256 + tt * 4]);
    }

    float4 acc = make_float4(0.f, 0.f, 0.f, 0.f);
    for (int e = start + half; e < end; e += 2) {
        const int s = __ldg(&src2[e]);
        const float4 v = *reinterpret_cast<const float4*>(&h[(size_t)s * 256 + tt * 4]);
        acc.x += v.x; acc.y += v.y; acc.z += v.z; acc.w += v.w;
    }
    *reinterpret_cast<float4*>(&a_nb[half][tt * 4]) = acc;
    __syncthreads();

    const int deg = end - start;
    const float inv = (deg > 0) ? 1.0f / (float)deg : 0.0f;
    if (half == 0) {
        float4 u = *reinterpret_cast<float4*>(&a_nb[0][tt * 4]);
        const float4 w = *reinterpret_cast<float4*>(&a_nb[1][tt * 4]);
        u.x = (u.x + w.x) * inv; u.y = (u.y + w.y) * inv;
        u.z = (u.z + w.z) * inv; u.w = (u.w + w.w) * inv;
        *reinterpret_cast<float4*>(&a_nb[0][tt * 4]) = u;
    }
    __syncthreads();

    if (t < 94) {
        const int c  = (t < 47) ? t : t - 47;
        const int kb = (t < 47) ? 0 : 128;
        const float* as = &a_self[kb];
        const float* an = &a_nb[0][kb];
        float accS = 0.f, accN = 0.f;
#pragma unroll 8
        for (int k = 0; k < 128; ++k) {
            accS += as[k] * __ldg(&Ws[(size_t)(kb + k) * 47 + c]);
            accN += an[k] * __ldg(&Wn[(size_t)(kb + k) * 47 + c]);
        }
        part[t] = accS + accN;
    }
    __syncthreads();

    if (t < 47) {
        out[(size_t)d * 47 + t] = part[t] + part[t + 47] + __ldg(&bias[t]);
    }
}

// ---------------------------------------------------------------------------
// Launch
// ---------------------------------------------------------------------------
extern "C" void kernel_launch(void* const* d_in, const int* in_sizes, int n_in,
                              void* d_out, int out_size)
{
    const float* x       = (const float*)d_in[0];
    const int*   src1    = (const int*)  d_in[1];
    const int*   dst1    = (const int*)  d_in[2];
    const int*   src2    = (const int*)  d_in[3];
    const int*   dst2    = (const int*)  d_in[4];
    const float* Wself1  = (const float*)d_in[5];
    const float* Wneigh1 = (const float*)d_in[6];
    const float* b1      = (const float*)d_in[7];
    const float* Wself2  = (const float*)d_in[8];
    const float* Wneigh2 = (const float*)d_in[9];
    const float* b2      = (const float*)d_in[10];
    float* out = (float*)d_out;

    __half *A, *WT;
    float* hbuf;
    cudaGetSymbolAddress((void**)&A,  g_A);
    cudaGetSymbolAddress((void**)&WT, g_WT);
    cudaGetSymbolAddress((void**)&hbuf, g_h);

    // Prep: W transpose+convert, x convert, neighbor mean (+convert)
    wcvt_kernel<<<(256 * 512) / 256, 256>>>(Wself1, Wneigh1, WT);
    xcvt_kernel<<<(N_DST1 * 64) / 256, 256>>>(x, A);
    agg1_kernel<<<N_DST1, 64>>>(x, src1, dst1, A);

    // Layer 1 GEMM + bias + relu (single-pass fp16)
    dim3 g1(H_DIM / G1_BN, N_DST1 / G1_BM);   // (4, 88)
    gemm1_kernel<<<g1, 256>>>(A, WT, b1, hbuf);

    // Fused layer 2
    layer2_fused_kernel<<<N_DST2, 128>>>(hbuf, src2, dst2, Wself2, Wneigh2, b2, out);
}